// round 2
// baseline (speedup 1.0000x reference)
#include <cuda_runtime.h>

#define THREADS 128
#define NF 64
#define ZIN 12
#define NOUT 16

// IDX[o][s] = sorted((o+s) % 16, s=0..7), baked at compile time (no runtime memcpy).
__constant__ int c_idx[NOUT][8] = {
    {0,1,2,3,4,5,6,7},
    {1,2,3,4,5,6,7,8},
    {2,3,4,5,6,7,8,9},
    {3,4,5,6,7,8,9,10},
    {4,5,6,7,8,9,10,11},
    {5,6,7,8,9,10,11,12},
    {6,7,8,9,10,11,12,13},
    {7,8,9,10,11,12,13,14},
    {8,9,10,11,12,13,14,15},
    {0,9,10,11,12,13,14,15},
    {0,1,10,11,12,13,14,15},
    {0,1,2,11,12,13,14,15},
    {0,1,2,3,12,13,14,15},
    {0,1,2,3,4,13,14,15},
    {0,1,2,3,4,5,14,15},
    {0,1,2,3,4,5,6,15}
};

// Accurate branch-free tanh: 2 MUFU (EX2, RCP) + ~4 FMA-pipe ops, ~1e-6 error.
// (MUFU.TANH approx would be ~5e-4 abs error -> ~8e-3 rel on dx: too coarse.)
__device__ __forceinline__ float fast_tanh(float x) {
    float e = __expf(x + x);
    return 1.0f - __fdividef(2.0f, e + 1.0f);
}

__global__ __launch_bounds__(THREADS)
void fans_kernel(const float* __restrict__ x_f,
                 const float* __restrict__ x_b,
                 const float* __restrict__ u,
                 const float* __restrict__ W0,
                 const float* __restrict__ W1,
                 const float* __restrict__ W2,
                 float* __restrict__ out)
{
    const int o   = blockIdx.y;
    const int tid = threadIdx.x;
    const int b   = blockIdx.x * THREADS + tid;

    __shared__ float sW0[NF * ZIN];     // 3 KB
    __shared__ float sW1[NF * NF];      // 16 KB
    __shared__ float sW2[NF];           // 256 B
    __shared__ float sxt[16 * THREADS]; // 8 KB scratch for runtime-indexed gather

    // ---- cooperative weight staging (vectorized) ----
    {
        const float4* g = (const float4*)(W1 + o * (NF * NF));
        float4*       s = (float4*)sW1;
        #pragma unroll
        for (int i = 0; i < (NF * NF / 4) / THREADS; i++)   // 8 iters
            s[tid + i * THREADS] = g[tid + i * THREADS];
    }
    {
        const float4* g = (const float4*)(W0 + o * (NF * ZIN));
        float4*       s = (float4*)sW0;
        for (int i = tid; i < NF * ZIN / 4; i += THREADS)   // 192 float4
            s[i] = g[i];
    }
    if (tid < NF) sW2[tid] = W2[o * NF + tid];

    // ---- per-thread input staging: x_tilde into smem column (own lane only,
    //      used purely so the runtime IDX gather doesn't force local memory) ----
    float4 f0 = *(const float4*)(x_f + b * 8);
    float4 f1 = *(const float4*)(x_f + b * 8 + 4);
    float4 g0 = *(const float4*)(x_b + b * 8);
    float4 g1 = *(const float4*)(x_b + b * 8 + 4);
    sxt[ 0 * THREADS + tid] = f0.x;  sxt[ 1 * THREADS + tid] = f0.y;
    sxt[ 2 * THREADS + tid] = f0.z;  sxt[ 3 * THREADS + tid] = f0.w;
    sxt[ 4 * THREADS + tid] = f1.x;  sxt[ 5 * THREADS + tid] = f1.y;
    sxt[ 6 * THREADS + tid] = f1.z;  sxt[ 7 * THREADS + tid] = f1.w;
    sxt[ 8 * THREADS + tid] = g0.x;  sxt[ 9 * THREADS + tid] = g0.y;
    sxt[10 * THREADS + tid] = g0.z;  sxt[11 * THREADS + tid] = g0.w;
    sxt[12 * THREADS + tid] = g1.x;  sxt[13 * THREADS + tid] = g1.y;
    sxt[14 * THREADS + tid] = g1.z;  sxt[15 * THREADS + tid] = g1.w;
    float4 uu = *(const float4*)(u + b * 4);

    __syncthreads();

    // ---- build z (12) ----
    float z[ZIN];
    #pragma unroll
    for (int s2 = 0; s2 < 8; s2++)
        z[s2] = sxt[c_idx[o][s2] * THREADS + tid];
    z[8] = uu.x; z[9] = uu.y; z[10] = uu.z; z[11] = uu.w;

    // ---- layer 1: h = tanh(W0 z), fully unrolled so h[64] stays in registers ----
    float h[NF];
    #pragma unroll
    for (int f = 0; f < NF; f++) {
        const float* w = &sW0[f * ZIN];
        float acc = 0.0f;
        #pragma unroll
        for (int i = 0; i < ZIN; i++)
            acc = fmaf(z[i], w[i], acc);
        h[f] = fast_tanh(acc);
    }

    // ---- layer 2 + 3 fused: dx = sum_f2 w2[f2] * tanh(W1[f2,:] . h) ----
    float dx = 0.0f;
    #pragma unroll 2
    for (int f2 = 0; f2 < NF; f2++) {
        const float* w = &sW1[f2 * NF];
        float a0 = 0.0f, a1 = 0.0f, a2 = 0.0f, a3 = 0.0f;
        #pragma unroll
        for (int f1 = 0; f1 < NF; f1 += 4) {
            a0 = fmaf(h[f1 + 0], w[f1 + 0], a0);
            a1 = fmaf(h[f1 + 1], w[f1 + 1], a1);
            a2 = fmaf(h[f1 + 2], w[f1 + 2], a2);
            a3 = fmaf(h[f1 + 3], w[f1 + 3], a3);
        }
        float hv = fast_tanh((a0 + a1) + (a2 + a3));
        dx = fmaf(hv, sW2[f2], dx);
    }

    out[b * NOUT + o] = dx;
}

extern "C" void kernel_launch(void* const* d_in, const int* in_sizes, int n_in,
                              void* d_out, int out_size) {
    const float* x_f = (const float*)d_in[0];
    const float* x_b = (const float*)d_in[1];
    const float* u   = (const float*)d_in[2];
    const float* W0  = (const float*)d_in[3];
    const float* W1  = (const float*)d_in[4];
    const float* W2  = (const float*)d_in[5];
    float* out = (float*)d_out;

    int B = in_sizes[0] / 8;                 // x_f is (B, 8)
    dim3 grid(B / THREADS, NOUT);
    fans_kernel<<<grid, THREADS>>>(x_f, x_b, u, W0, W1, W2, out);
}

// round 3
// speedup vs baseline: 1.0012x; 1.0012x over previous
#include <cuda_runtime.h>

#define THREADS 128
#define NF 64
#define ZIN 12
#define NOUT 16

// IDX[o][s] = sorted((o+s) % 16, s=0..7), baked at compile time (no runtime memcpy).
__constant__ int c_idx[NOUT][8] = {
    {0,1,2,3,4,5,6,7},
    {1,2,3,4,5,6,7,8},
    {2,3,4,5,6,7,8,9},
    {3,4,5,6,7,8,9,10},
    {4,5,6,7,8,9,10,11},
    {5,6,7,8,9,10,11,12},
    {6,7,8,9,10,11,12,13},
    {7,8,9,10,11,12,13,14},
    {8,9,10,11,12,13,14,15},
    {0,9,10,11,12,13,14,15},
    {0,1,10,11,12,13,14,15},
    {0,1,2,11,12,13,14,15},
    {0,1,2,3,12,13,14,15},
    {0,1,2,3,4,13,14,15},
    {0,1,2,3,4,5,14,15},
    {0,1,2,3,4,5,6,15}
};

// Accurate branch-free tanh: 2 MUFU (EX2, RCP) + ~4 FMA-pipe ops, ~1e-6 error.
// (MUFU.TANH approx would be ~5e-4 abs error -> ~8e-3 rel on dx: too coarse.)
__device__ __forceinline__ float fast_tanh(float x) {
    float e = __expf(x + x);
    return 1.0f - __fdividef(2.0f, e + 1.0f);
}

__global__ __launch_bounds__(THREADS)
void fans_kernel(const float* __restrict__ x_f,
                 const float* __restrict__ x_b,
                 const float* __restrict__ u,
                 const float* __restrict__ W0,
                 const float* __restrict__ W1,
                 const float* __restrict__ W2,
                 float* __restrict__ out)
{
    const int o   = blockIdx.y;
    const int tid = threadIdx.x;
    const int b   = blockIdx.x * THREADS + tid;

    __shared__ float sW0[NF * ZIN];     // 3 KB
    __shared__ float sW1[NF * NF];      // 16 KB
    __shared__ float sW2[NF];           // 256 B
    __shared__ float sxt[16 * THREADS]; // 8 KB scratch for runtime-indexed gather

    // ---- cooperative weight staging (vectorized) ----
    {
        const float4* g = (const float4*)(W1 + o * (NF * NF));
        float4*       s = (float4*)sW1;
        #pragma unroll
        for (int i = 0; i < (NF * NF / 4) / THREADS; i++)   // 8 iters
            s[tid + i * THREADS] = g[tid + i * THREADS];
    }
    {
        const float4* g = (const float4*)(W0 + o * (NF * ZIN));
        float4*       s = (float4*)sW0;
        for (int i = tid; i < NF * ZIN / 4; i += THREADS)   // 192 float4
            s[i] = g[i];
    }
    if (tid < NF) sW2[tid] = W2[o * NF + tid];

    // ---- per-thread input staging: x_tilde into smem column (own lane only,
    //      used purely so the runtime IDX gather doesn't force local memory) ----
    float4 f0 = *(const float4*)(x_f + b * 8);
    float4 f1 = *(const float4*)(x_f + b * 8 + 4);
    float4 g0 = *(const float4*)(x_b + b * 8);
    float4 g1 = *(const float4*)(x_b + b * 8 + 4);
    sxt[ 0 * THREADS + tid] = f0.x;  sxt[ 1 * THREADS + tid] = f0.y;
    sxt[ 2 * THREADS + tid] = f0.z;  sxt[ 3 * THREADS + tid] = f0.w;
    sxt[ 4 * THREADS + tid] = f1.x;  sxt[ 5 * THREADS + tid] = f1.y;
    sxt[ 6 * THREADS + tid] = f1.z;  sxt[ 7 * THREADS + tid] = f1.w;
    sxt[ 8 * THREADS + tid] = g0.x;  sxt[ 9 * THREADS + tid] = g0.y;
    sxt[10 * THREADS + tid] = g0.z;  sxt[11 * THREADS + tid] = g0.w;
    sxt[12 * THREADS + tid] = g1.x;  sxt[13 * THREADS + tid] = g1.y;
    sxt[14 * THREADS + tid] = g1.z;  sxt[15 * THREADS + tid] = g1.w;
    float4 uu = *(const float4*)(u + b * 4);

    __syncthreads();

    // ---- build z (12) ----
    float z[ZIN];
    #pragma unroll
    for (int s2 = 0; s2 < 8; s2++)
        z[s2] = sxt[c_idx[o][s2] * THREADS + tid];
    z[8] = uu.x; z[9] = uu.y; z[10] = uu.z; z[11] = uu.w;

    // ---- layer 1: h = tanh(W0 z), fully unrolled so h[64] stays in registers ----
    float h[NF];
    #pragma unroll
    for (int f = 0; f < NF; f++) {
        const float* w = &sW0[f * ZIN];
        float acc = 0.0f;
        #pragma unroll
        for (int i = 0; i < ZIN; i++)
            acc = fmaf(z[i], w[i], acc);
        h[f] = fast_tanh(acc);
    }

    // ---- layer 2 + 3 fused: dx = sum_f2 w2[f2] * tanh(W1[f2,:] . h) ----
    float dx = 0.0f;
    #pragma unroll 2
    for (int f2 = 0; f2 < NF; f2++) {
        const float* w = &sW1[f2 * NF];
        float a0 = 0.0f, a1 = 0.0f, a2 = 0.0f, a3 = 0.0f;
        #pragma unroll
        for (int f1 = 0; f1 < NF; f1 += 4) {
            a0 = fmaf(h[f1 + 0], w[f1 + 0], a0);
            a1 = fmaf(h[f1 + 1], w[f1 + 1], a1);
            a2 = fmaf(h[f1 + 2], w[f1 + 2], a2);
            a3 = fmaf(h[f1 + 3], w[f1 + 3], a3);
        }
        float hv = fast_tanh((a0 + a1) + (a2 + a3));
        dx = fmaf(hv, sW2[f2], dx);
    }

    out[b * NOUT + o] = dx;
}

extern "C" void kernel_launch(void* const* d_in, const int* in_sizes, int n_in,
                              void* d_out, int out_size) {
    const float* x_f = (const float*)d_in[0];
    const float* x_b = (const float*)d_in[1];
    const float* u   = (const float*)d_in[2];
    const float* W0  = (const float*)d_in[3];
    const float* W1  = (const float*)d_in[4];
    const float* W2  = (const float*)d_in[5];
    float* out = (float*)d_out;

    int B = in_sizes[0] / 8;                 // x_f is (B, 8)
    dim3 grid(B / THREADS, NOUT);
    fans_kernel<<<grid, THREADS>>>(x_f, x_b, u, W0, W1, W2, out);
}

// round 4
// speedup vs baseline: 1.0185x; 1.0172x over previous
#include <cuda_runtime.h>

#define THREADS 128
#define NF 64
#define ZIN 12
#define NOUT 16

typedef unsigned long long ull;

// IDX[o][s] = sorted((o+s) % 16, s=0..7), baked at compile time.
__constant__ int c_idx[NOUT][8] = {
    {0,1,2,3,4,5,6,7},
    {1,2,3,4,5,6,7,8},
    {2,3,4,5,6,7,8,9},
    {3,4,5,6,7,8,9,10},
    {4,5,6,7,8,9,10,11},
    {5,6,7,8,9,10,11,12},
    {6,7,8,9,10,11,12,13},
    {7,8,9,10,11,12,13,14},
    {8,9,10,11,12,13,14,15},
    {0,9,10,11,12,13,14,15},
    {0,1,10,11,12,13,14,15},
    {0,1,2,11,12,13,14,15},
    {0,1,2,3,12,13,14,15},
    {0,1,2,3,4,13,14,15},
    {0,1,2,3,4,5,14,15},
    {0,1,2,3,4,5,6,15}
};

// ---- packed f32x2 helpers (FFMA2: the pattern ptxas won't auto-emit) ----
__device__ __forceinline__ ull fma2(ull a, ull b, ull c) {
    ull d;
    asm("fma.rn.f32x2 %0, %1, %2, %3;" : "=l"(d) : "l"(a), "l"(b), "l"(c));
    return d;
}
__device__ __forceinline__ ull pack2(float lo, float hi) {
    ull r;
    asm("mov.b64 %0, {%1, %2};" : "=l"(r) : "f"(lo), "f"(hi));
    return r;
}
__device__ __forceinline__ float2 unpack2(ull v) {
    float2 r;
    asm("mov.b64 {%0, %1}, %2;" : "=f"(r.x), "=f"(r.y) : "l"(v));
    return r;
}

// Accurate branch-free tanh: 2 MUFU (EX2, RCP) + ~4 FMA-pipe ops, ~1e-6 error.
__device__ __forceinline__ float fast_tanh(float x) {
    float e = __expf(x + x);
    return 1.0f - __fdividef(2.0f, e + 1.0f);
}

__global__ __launch_bounds__(THREADS)
void fans_kernel(const float* __restrict__ x_f,
                 const float* __restrict__ x_b,
                 const float* __restrict__ u,
                 const float* __restrict__ W0,
                 const float* __restrict__ W1,
                 const float* __restrict__ W2,
                 float* __restrict__ out)
{
    const int o   = blockIdx.y;
    const int tid = threadIdx.x;
    const int b   = blockIdx.x * THREADS + tid;

    __shared__ float sW0[NF * ZIN];     // 3 KB   (rows of 12 floats = 48B, 16B-aligned)
    __shared__ float sW1[NF * NF];      // 16 KB
    __shared__ float sW2[NF];           // 256 B
    __shared__ float sxt[16 * THREADS]; // 8 KB scratch for runtime-indexed gather

    // ---- cooperative weight staging (vectorized) ----
    {
        const float4* g = (const float4*)(W1 + o * (NF * NF));
        float4*       s = (float4*)sW1;
        #pragma unroll
        for (int i = 0; i < (NF * NF / 4) / THREADS; i++)   // 8 iters
            s[tid + i * THREADS] = g[tid + i * THREADS];
    }
    {
        const float4* g = (const float4*)(W0 + o * (NF * ZIN));
        float4*       s = (float4*)sW0;
        for (int i = tid; i < NF * ZIN / 4; i += THREADS)   // 192 float4
            s[i] = g[i];
    }
    if (tid < NF) sW2[tid] = W2[o * NF + tid];

    // ---- per-thread input staging: x_tilde into smem column ----
    float4 f0 = *(const float4*)(x_f + b * 8);
    float4 f1 = *(const float4*)(x_f + b * 8 + 4);
    float4 g0 = *(const float4*)(x_b + b * 8);
    float4 g1 = *(const float4*)(x_b + b * 8 + 4);
    sxt[ 0 * THREADS + tid] = f0.x;  sxt[ 1 * THREADS + tid] = f0.y;
    sxt[ 2 * THREADS + tid] = f0.z;  sxt[ 3 * THREADS + tid] = f0.w;
    sxt[ 4 * THREADS + tid] = f1.x;  sxt[ 5 * THREADS + tid] = f1.y;
    sxt[ 6 * THREADS + tid] = f1.z;  sxt[ 7 * THREADS + tid] = f1.w;
    sxt[ 8 * THREADS + tid] = g0.x;  sxt[ 9 * THREADS + tid] = g0.y;
    sxt[10 * THREADS + tid] = g0.z;  sxt[11 * THREADS + tid] = g0.w;
    sxt[12 * THREADS + tid] = g1.x;  sxt[13 * THREADS + tid] = g1.y;
    sxt[14 * THREADS + tid] = g1.z;  sxt[15 * THREADS + tid] = g1.w;
    float4 uu = *(const float4*)(u + b * 4);

    __syncthreads();

    // ---- build z (12 scalars -> 6 packed pairs) ----
    float z[ZIN];
    #pragma unroll
    for (int s2 = 0; s2 < 8; s2++)
        z[s2] = sxt[c_idx[o][s2] * THREADS + tid];
    z[8] = uu.x; z[9] = uu.y; z[10] = uu.z; z[11] = uu.w;

    ull zp[ZIN / 2];
    #pragma unroll
    for (int i = 0; i < ZIN / 2; i++)
        zp[i] = pack2(z[2 * i], z[2 * i + 1]);

    // ---- layer 1: h = tanh(W0 z) via packed FFMA2, h packed in 32 b64 regs ----
    ull h2[NF / 2];
    #pragma unroll
    for (int f = 0; f < NF; f += 2) {
        const ulonglong2* wA = (const ulonglong2*)(&sW0[(f + 0) * ZIN]); // 48B-aligned
        const ulonglong2* wB = (const ulonglong2*)(&sW0[(f + 1) * ZIN]);
        ull accA = 0ull, accB = 0ull;
        #pragma unroll
        for (int i = 0; i < 3; i++) {
            ulonglong2 qA = wA[i];
            ulonglong2 qB = wB[i];
            accA = fma2(zp[2 * i + 0], qA.x, accA);
            accA = fma2(zp[2 * i + 1], qA.y, accA);
            accB = fma2(zp[2 * i + 0], qB.x, accB);
            accB = fma2(zp[2 * i + 1], qB.y, accB);
        }
        float2 sA = unpack2(accA);
        float2 sB = unpack2(accB);
        float hA = fast_tanh(sA.x + sA.y);
        float hB = fast_tanh(sB.x + sB.y);
        h2[f / 2] = pack2(hA, hB);
    }

    // ---- layer 2 + 3 fused: dx = sum_f2 w2[f2] * tanh(W1[f2,:] . h) ----
    // Inner dot: 16 LDS.128 (2 packed weight-pairs each) + 32 FFMA2 per f2 row.
    float dx = 0.0f;
    #pragma unroll 2
    for (int f2 = 0; f2 < NF; f2++) {
        const ulonglong2* w = (const ulonglong2*)(&sW1[f2 * NF]);
        ull a0 = 0ull, a1 = 0ull, a2 = 0ull, a3 = 0ull;
        #pragma unroll
        for (int j = 0; j < 16; j += 2) {
            ulonglong2 q0 = w[j + 0];
            ulonglong2 q1 = w[j + 1];
            a0 = fma2(h2[2 * j + 0], q0.x, a0);
            a1 = fma2(h2[2 * j + 1], q0.y, a1);
            a2 = fma2(h2[2 * j + 2], q1.x, a2);
            a3 = fma2(h2[2 * j + 3], q1.y, a3);
        }
        float2 s0 = unpack2(a0);
        float2 s1 = unpack2(a1);
        float2 s2 = unpack2(a2);
        float2 s3 = unpack2(a3);
        float s = ((s0.x + s0.y) + (s1.x + s1.y)) + ((s2.x + s2.y) + (s3.x + s3.y));
        dx = fmaf(fast_tanh(s), sW2[f2], dx);
    }

    out[b * NOUT + o] = dx;
}

extern "C" void kernel_launch(void* const* d_in, const int* in_sizes, int n_in,
                              void* d_out, int out_size) {
    const float* x_f = (const float*)d_in[0];
    const float* x_b = (const float*)d_in[1];
    const float* u   = (const float*)d_in[2];
    const float* W0  = (const float*)d_in[3];
    const float* W1  = (const float*)d_in[4];
    const float* W2  = (const float*)d_in[5];
    float* out = (float*)d_out;

    int B = in_sizes[0] / 8;                 // x_f is (B, 8)
    dim3 grid(B / THREADS, NOUT);
    fans_kernel<<<grid, THREADS>>>(x_f, x_b, u, W0, W1, W2, out);
}

// round 5
// speedup vs baseline: 1.0329x; 1.0142x over previous
#include <cuda_runtime.h>

#define THREADS 128
#define ROWS 2           // batch rows per thread: weight LDS amortization
#define NF 64
#define ZIN 12
#define NOUT 16

typedef unsigned long long ull;

// IDX[o][s] = sorted((o+s) % 16, s=0..7), baked at compile time.
__constant__ int c_idx[NOUT][8] = {
    {0,1,2,3,4,5,6,7},
    {1,2,3,4,5,6,7,8},
    {2,3,4,5,6,7,8,9},
    {3,4,5,6,7,8,9,10},
    {4,5,6,7,8,9,10,11},
    {5,6,7,8,9,10,11,12},
    {6,7,8,9,10,11,12,13},
    {7,8,9,10,11,12,13,14},
    {8,9,10,11,12,13,14,15},
    {0,9,10,11,12,13,14,15},
    {0,1,10,11,12,13,14,15},
    {0,1,2,11,12,13,14,15},
    {0,1,2,3,12,13,14,15},
    {0,1,2,3,4,13,14,15},
    {0,1,2,3,4,5,14,15},
    {0,1,2,3,4,5,6,15}
};

// ---- packed f32x2 helpers (FFMA2) ----
__device__ __forceinline__ ull fma2(ull a, ull b, ull c) {
    ull d;
    asm("fma.rn.f32x2 %0, %1, %2, %3;" : "=l"(d) : "l"(a), "l"(b), "l"(c));
    return d;
}
__device__ __forceinline__ ull pack2(float lo, float hi) {
    ull r;
    asm("mov.b64 %0, {%1, %2};" : "=l"(r) : "f"(lo), "f"(hi));
    return r;
}
__device__ __forceinline__ float2 unpack2(ull v) {
    float2 r;
    asm("mov.b64 {%0, %1}, %2;" : "=f"(r.x), "=f"(r.y) : "l"(v));
    return r;
}

// Accurate branch-free tanh: 2 MUFU (EX2, RCP) + ~4 FMA-pipe ops, ~1e-6 error.
__device__ __forceinline__ float fast_tanh(float x) {
    float e = __expf(x + x);
    return 1.0f - __fdividef(2.0f, e + 1.0f);
}

__global__ __launch_bounds__(THREADS)
void fans_kernel(const float* __restrict__ x_f,
                 const float* __restrict__ x_b,
                 const float* __restrict__ u,
                 const float* __restrict__ W0,
                 const float* __restrict__ W1,
                 const float* __restrict__ W2,
                 float* __restrict__ out)
{
    const int o   = blockIdx.y;
    const int tid = threadIdx.x;
    const int b0  = blockIdx.x * (THREADS * ROWS) + tid;
    const int b1  = b0 + THREADS;

    __shared__ float sW0[NF * ZIN];              // 3 KB (rows of 48B, 16B aligned)
    __shared__ float sW1[NF * NF];               // 16 KB
    __shared__ float sW2[NF];                    // 256 B
    __shared__ float sxt[16 * (THREADS * ROWS)]; // 16 KB gather scratch, 2 rows

    // ---- cooperative weight staging (vectorized) ----
    {
        const float4* g = (const float4*)(W1 + o * (NF * NF));
        float4*       s = (float4*)sW1;
        #pragma unroll
        for (int i = 0; i < (NF * NF / 4) / THREADS; i++)   // 8 iters
            s[tid + i * THREADS] = g[tid + i * THREADS];
    }
    {
        const float4* g = (const float4*)(W0 + o * (NF * ZIN));
        float4*       s = (float4*)sW0;
        for (int i = tid; i < NF * ZIN / 4; i += THREADS)   // 192 float4
            s[i] = g[i];
    }
    if (tid < NF) sW2[tid] = W2[o * NF + tid];

    // ---- per-thread input staging: x_tilde for both rows into smem columns ----
    const int C = THREADS * ROWS;   // 256 columns
    {
        float4 f0 = *(const float4*)(x_f + b0 * 8);
        float4 f1 = *(const float4*)(x_f + b0 * 8 + 4);
        float4 g0 = *(const float4*)(x_b + b0 * 8);
        float4 g1 = *(const float4*)(x_b + b0 * 8 + 4);
        int c = tid;
        sxt[ 0*C + c] = f0.x;  sxt[ 1*C + c] = f0.y;
        sxt[ 2*C + c] = f0.z;  sxt[ 3*C + c] = f0.w;
        sxt[ 4*C + c] = f1.x;  sxt[ 5*C + c] = f1.y;
        sxt[ 6*C + c] = f1.z;  sxt[ 7*C + c] = f1.w;
        sxt[ 8*C + c] = g0.x;  sxt[ 9*C + c] = g0.y;
        sxt[10*C + c] = g0.z;  sxt[11*C + c] = g0.w;
        sxt[12*C + c] = g1.x;  sxt[13*C + c] = g1.y;
        sxt[14*C + c] = g1.z;  sxt[15*C + c] = g1.w;
    }
    {
        float4 f0 = *(const float4*)(x_f + b1 * 8);
        float4 f1 = *(const float4*)(x_f + b1 * 8 + 4);
        float4 g0 = *(const float4*)(x_b + b1 * 8);
        float4 g1 = *(const float4*)(x_b + b1 * 8 + 4);
        int c = tid + THREADS;
        sxt[ 0*C + c] = f0.x;  sxt[ 1*C + c] = f0.y;
        sxt[ 2*C + c] = f0.z;  sxt[ 3*C + c] = f0.w;
        sxt[ 4*C + c] = f1.x;  sxt[ 5*C + c] = f1.y;
        sxt[ 6*C + c] = f1.z;  sxt[ 7*C + c] = f1.w;
        sxt[ 8*C + c] = g0.x;  sxt[ 9*C + c] = g0.y;
        sxt[10*C + c] = g0.z;  sxt[11*C + c] = g0.w;
        sxt[12*C + c] = g1.x;  sxt[13*C + c] = g1.y;
        sxt[14*C + c] = g1.z;  sxt[15*C + c] = g1.w;
    }
    float4 u0 = *(const float4*)(u + b0 * 4);
    float4 u1 = *(const float4*)(u + b1 * 4);

    __syncthreads();

    // ---- build z for both rows (12 scalars -> 6 packed pairs each) ----
    ull zp0[ZIN / 2], zp1[ZIN / 2];
    {
        float z0[ZIN], z1[ZIN];
        #pragma unroll
        for (int s2 = 0; s2 < 8; s2++) {
            int r = c_idx[o][s2] * C;
            z0[s2] = sxt[r + tid];
            z1[s2] = sxt[r + tid + THREADS];
        }
        z0[8] = u0.x; z0[9] = u0.y; z0[10] = u0.z; z0[11] = u0.w;
        z1[8] = u1.x; z1[9] = u1.y; z1[10] = u1.z; z1[11] = u1.w;
        #pragma unroll
        for (int i = 0; i < ZIN / 2; i++) {
            zp0[i] = pack2(z0[2*i], z0[2*i+1]);
            zp1[i] = pack2(z1[2*i], z1[2*i+1]);
        }
    }

    // ---- layer 1: h = tanh(W0 z) for both rows; weights loaded once per pair ----
    ull hA[NF / 2], hB[NF / 2];      // packed h pairs, row0 / row1
    #pragma unroll
    for (int f = 0; f < NF; f += 2) {
        const ulonglong2* wA = (const ulonglong2*)(&sW0[(f + 0) * ZIN]);
        const ulonglong2* wB = (const ulonglong2*)(&sW0[(f + 1) * ZIN]);
        ull aA = 0ull, aB = 0ull;    // row0: features f, f+1
        ull bA = 0ull, bB = 0ull;    // row1: features f, f+1
        #pragma unroll
        for (int i = 0; i < 3; i++) {
            ulonglong2 qA = wA[i];
            ulonglong2 qB = wB[i];
            aA = fma2(zp0[2*i+0], qA.x, aA);
            aA = fma2(zp0[2*i+1], qA.y, aA);
            aB = fma2(zp0[2*i+0], qB.x, aB);
            aB = fma2(zp0[2*i+1], qB.y, aB);
            bA = fma2(zp1[2*i+0], qA.x, bA);
            bA = fma2(zp1[2*i+1], qA.y, bA);
            bB = fma2(zp1[2*i+0], qB.x, bB);
            bB = fma2(zp1[2*i+1], qB.y, bB);
        }
        float2 sA = unpack2(aA), sB = unpack2(aB);
        float2 tA = unpack2(bA), tB = unpack2(bB);
        hA[f / 2] = pack2(fast_tanh(sA.x + sA.y), fast_tanh(sB.x + sB.y));
        hB[f / 2] = pack2(fast_tanh(tA.x + tA.y), fast_tanh(tB.x + tB.y));
    }

    // ---- layer 2 + 3 fused, both rows share each W1-row load ----
    float dx0 = 0.0f, dx1 = 0.0f;
    #pragma unroll 2
    for (int f2 = 0; f2 < NF; f2++) {
        const ulonglong2* w = (const ulonglong2*)(&sW1[f2 * NF]);
        ull a0 = 0ull, a1 = 0ull, a2 = 0ull, a3 = 0ull;   // row0
        ull c0 = 0ull, c1 = 0ull, c2 = 0ull, c3 = 0ull;   // row1
        #pragma unroll
        for (int j = 0; j < 16; j += 2) {
            ulonglong2 q0 = w[j + 0];
            ulonglong2 q1 = w[j + 1];
            a0 = fma2(hA[2*j + 0], q0.x, a0);
            a1 = fma2(hA[2*j + 1], q0.y, a1);
            a2 = fma2(hA[2*j + 2], q1.x, a2);
            a3 = fma2(hA[2*j + 3], q1.y, a3);
            c0 = fma2(hB[2*j + 0], q0.x, c0);
            c1 = fma2(hB[2*j + 1], q0.y, c1);
            c2 = fma2(hB[2*j + 2], q1.x, c2);
            c3 = fma2(hB[2*j + 3], q1.y, c3);
        }
        float w2v = sW2[f2];
        {
            float2 s0 = unpack2(a0), s1 = unpack2(a1);
            float2 s2 = unpack2(a2), s3 = unpack2(a3);
            float s = ((s0.x + s0.y) + (s1.x + s1.y)) + ((s2.x + s2.y) + (s3.x + s3.y));
            dx0 = fmaf(fast_tanh(s), w2v, dx0);
        }
        {
            float2 s0 = unpack2(c0), s1 = unpack2(c1);
            float2 s2 = unpack2(c2), s3 = unpack2(c3);
            float s = ((s0.x + s0.y) + (s1.x + s1.y)) + ((s2.x + s2.y) + (s3.x + s3.y));
            dx1 = fmaf(fast_tanh(s), w2v, dx1);
        }
    }

    out[b0 * NOUT + o] = dx0;
    out[b1 * NOUT + o] = dx1;
}

extern "C" void kernel_launch(void* const* d_in, const int* in_sizes, int n_in,
                              void* d_out, int out_size) {
    const float* x_f = (const float*)d_in[0];
    const float* x_b = (const float*)d_in[1];
    const float* u   = (const float*)d_in[2];
    const float* W0  = (const float*)d_in[3];
    const float* W1  = (const float*)d_in[4];
    const float* W2  = (const float*)d_in[5];
    float* out = (float*)d_out;

    int B = in_sizes[0] / 8;                      // x_f is (B, 8)
    dim3 grid(B / (THREADS * ROWS), NOUT);
    fans_kernel<<<grid, THREADS>>>(x_f, x_b, u, W0, W1, W2, out);
}

// round 7
// speedup vs baseline: 1.1977x; 1.1595x over previous
#include <cuda_runtime.h>

#define THREADS 128
#define ROWS 2           // batch rows per thread: weight LDS amortization
#define NF 64
#define ZIN 12
#define NOUT 16

typedef unsigned long long ull;

// ---- packed f32x2 helpers (FFMA2) ----
__device__ __forceinline__ ull fma2(ull a, ull b, ull c) {
    ull d;
    asm("fma.rn.f32x2 %0, %1, %2, %3;" : "=l"(d) : "l"(a), "l"(b), "l"(c));
    return d;
}
__device__ __forceinline__ ull pack2(float lo, float hi) {
    ull r;
    asm("mov.b64 %0, {%1, %2};" : "=l"(r) : "f"(lo), "f"(hi));
    return r;
}
__device__ __forceinline__ float2 unpack2(ull v) {
    float2 r;
    asm("mov.b64 {%0, %1}, %2;" : "=f"(r.x), "=f"(r.y) : "l"(v));
    return r;
}

// Accurate branch-free tanh: 2 MUFU (EX2, RCP) + ~4 FMA-pipe ops, ~1e-6 error.
__device__ __forceinline__ float fast_tanh(float x) {
    float e = __expf(x + x);
    return 1.0f - __fdividef(2.0f, e + 1.0f);
}

__global__ __launch_bounds__(THREADS, 3)
void fans_kernel(const float* __restrict__ x_f,
                 const float* __restrict__ x_b,
                 const float* __restrict__ u,
                 const float* __restrict__ W0,
                 const float* __restrict__ W1,
                 const float* __restrict__ W2,
                 float* __restrict__ out)
{
    const int o   = blockIdx.y;
    const int tid = threadIdx.x;
    const int b0  = blockIdx.x * (THREADS * ROWS) + tid;
    const int b1  = b0 + THREADS;

    __shared__ float sW0[NF * ZIN];   // 3 KB (rows of 48B, 16B aligned)
    __shared__ float sW1[NF * NF];    // 16 KB
    __shared__ float sW2[NF];         // 256 B

    // ---- cooperative weight staging (vectorized) ----
    {
        const float4* g = (const float4*)(W1 + o * (NF * NF));
        float4*       s = (float4*)sW1;
        #pragma unroll
        for (int i = 0; i < (NF * NF / 4) / THREADS; i++)   // 8 iters
            s[tid + i * THREADS] = g[tid + i * THREADS];
    }
    {
        const float4* g = (const float4*)(W0 + o * (NF * ZIN));
        float4*       s = (float4*)sW0;
        for (int i = tid; i < NF * ZIN / 4; i += THREADS)   // 192 float4
            s[i] = g[i];
    }
    if (tid < NF) sW2[tid] = W2[o * NF + tid];

    // ---- build z for both rows directly from global (closed-form sorted IDX):
    //      o<=8 : e = o+s ;  o>=9 : e = (s < o-8) ? s : s+8
    //      element e<8 -> x_f[b*8+e], else x_b[b*8+e-8]. No smem, no dyn-index. ----
    ull zp0[ZIN / 2], zp1[ZIN / 2];
    {
        float z0[ZIN], z1[ZIN];
        #pragma unroll
        for (int s = 0; s < 8; s++) {
            int e = (o <= 8) ? (o + s) : ((s < o - 8) ? s : s + 8);
            const float* p = (e < 8) ? (x_f + e) : (x_b + (e - 8));
            z0[s] = __ldg(p + b0 * 8);
            z1[s] = __ldg(p + b1 * 8);
        }
        float4 u0 = *(const float4*)(u + b0 * 4);
        float4 u1 = *(const float4*)(u + b1 * 4);
        z0[8] = u0.x; z0[9] = u0.y; z0[10] = u0.z; z0[11] = u0.w;
        z1[8] = u1.x; z1[9] = u1.y; z1[10] = u1.z; z1[11] = u1.w;
        #pragma unroll
        for (int i = 0; i < ZIN / 2; i++) {
            zp0[i] = pack2(z0[2*i], z0[2*i+1]);
            zp1[i] = pack2(z1[2*i], z1[2*i+1]);
        }
    }

    __syncthreads();   // weights visible

    // ---- layer 1: h = tanh(W0 z) for both rows; weights loaded once per pair ----
    ull hA[NF / 2], hB[NF / 2];      // packed h pairs, row0 / row1
    #pragma unroll
    for (int f = 0; f < NF; f += 2) {
        const ulonglong2* wA = (const ulonglong2*)(&sW0[(f + 0) * ZIN]);
        const ulonglong2* wB = (const ulonglong2*)(&sW0[(f + 1) * ZIN]);
        ull aA = 0ull, aB = 0ull;    // row0: features f, f+1
        ull bA = 0ull, bB = 0ull;    // row1: features f, f+1
        #pragma unroll
        for (int i = 0; i < 3; i++) {
            ulonglong2 qA = wA[i];
            ulonglong2 qB = wB[i];
            aA = fma2(zp0[2*i+0], qA.x, aA);
            aA = fma2(zp0[2*i+1], qA.y, aA);
            aB = fma2(zp0[2*i+0], qB.x, aB);
            aB = fma2(zp0[2*i+1], qB.y, aB);
            bA = fma2(zp1[2*i+0], qA.x, bA);
            bA = fma2(zp1[2*i+1], qA.y, bA);
            bB = fma2(zp1[2*i+0], qB.x, bB);
            bB = fma2(zp1[2*i+1], qB.y, bB);
        }
        float2 sA = unpack2(aA), sB = unpack2(aB);
        float2 tA = unpack2(bA), tB = unpack2(bB);
        hA[f / 2] = pack2(fast_tanh(sA.x + sA.y), fast_tanh(sB.x + sB.y));
        hB[f / 2] = pack2(fast_tanh(tA.x + tA.y), fast_tanh(tB.x + tB.y));
    }

    // ---- layer 2 + 3 fused, both rows share each W1-row load ----
    float dx0 = 0.0f, dx1 = 0.0f;
    #pragma unroll 2
    for (int f2 = 0; f2 < NF; f2++) {
        const ulonglong2* w = (const ulonglong2*)(&sW1[f2 * NF]);
        ull a0 = 0ull, a1 = 0ull, a2 = 0ull, a3 = 0ull;   // row0
        ull c0 = 0ull, c1 = 0ull, c2 = 0ull, c3 = 0ull;   // row1
        #pragma unroll
        for (int j = 0; j < 16; j += 2) {
            ulonglong2 q0 = w[j + 0];
            ulonglong2 q1 = w[j + 1];
            a0 = fma2(hA[2*j + 0], q0.x, a0);
            a1 = fma2(hA[2*j + 1], q0.y, a1);
            a2 = fma2(hA[2*j + 2], q1.x, a2);
            a3 = fma2(hA[2*j + 3], q1.y, a3);
            c0 = fma2(hB[2*j + 0], q0.x, c0);
            c1 = fma2(hB[2*j + 1], q0.y, c1);
            c2 = fma2(hB[2*j + 2], q1.x, c2);
            c3 = fma2(hB[2*j + 3], q1.y, c3);
        }
        float w2v = sW2[f2];
        {
            float2 s0 = unpack2(a0), s1 = unpack2(a1);
            float2 s2 = unpack2(a2), s3 = unpack2(a3);
            float s = ((s0.x + s0.y) + (s1.x + s1.y)) + ((s2.x + s2.y) + (s3.x + s3.y));
            dx0 = fmaf(fast_tanh(s), w2v, dx0);
        }
        {
            float2 s0 = unpack2(c0), s1 = unpack2(c1);
            float2 s2 = unpack2(c2), s3 = unpack2(c3);
            float s = ((s0.x + s0.y) + (s1.x + s1.y)) + ((s2.x + s2.y) + (s3.x + s3.y));
            dx1 = fmaf(fast_tanh(s), w2v, dx1);
        }
    }

    out[b0 * NOUT + o] = dx0;
    out[b1 * NOUT + o] = dx1;
}

extern "C" void kernel_launch(void* const* d_in, const int* in_sizes, int n_in,
                              void* d_out, int out_size) {
    const float* x_f = (const float*)d_in[0];
    const float* x_b = (const float*)d_in[1];
    const float* u   = (const float*)d_in[2];
    const float* W0  = (const float*)d_in[3];
    const float* W1  = (const float*)d_in[4];
    const float* W2  = (const float*)d_in[5];
    float* out = (float*)d_out;

    int B = in_sizes[0] / 8;                      // x_f is (B, 8)
    dim3 grid(B / (THREADS * ROWS), NOUT);
    fans_kernel<<<grid, THREADS>>>(x_f, x_b, u, W0, W1, W2, out);
}

// round 8
// speedup vs baseline: 1.2462x; 1.0405x over previous
#include <cuda_runtime.h>

#define THREADS 128
#define ROWS 2           // batch rows per thread: weight LDS amortization
#define NF 64
#define ZIN 12
#define NOUT 16

typedef unsigned long long ull;

// ---- packed f32x2 helpers ----
__device__ __forceinline__ ull fma2(ull a, ull b, ull c) {
    ull d;
    asm("fma.rn.f32x2 %0, %1, %2, %3;" : "=l"(d) : "l"(a), "l"(b), "l"(c));
    return d;
}
__device__ __forceinline__ ull add2(ull a, ull b) {
    ull d;
    asm("add.rn.f32x2 %0, %1, %2;" : "=l"(d) : "l"(a), "l"(b));
    return d;
}
__device__ __forceinline__ ull pack2(float lo, float hi) {
    ull r;
    asm("mov.b64 %0, {%1, %2};" : "=l"(r) : "f"(lo), "f"(hi));
    return r;
}
__device__ __forceinline__ float2 unpack2(ull v) {
    float2 r;
    asm("mov.b64 {%0, %1}, %2;" : "=f"(r.x), "=f"(r.y) : "l"(v));
    return r;
}

// tanh(x) = 1 - 2*rcp(2^(x*2log2e) + 1): 3 fma-pipe ops + 2 MUFU, ~1e-6 err
// (same ex2/rcp.approx primitives __expf/__fdividef use, minus 2 extra ops).
__device__ __forceinline__ float fast_tanh(float x) {
    float t = x * 2.8853900817779268f;   // 2*log2(e)
    float e;
    asm("ex2.approx.f32 %0, %1;" : "=f"(e) : "f"(t));
    float d = e + 1.0f;
    float r;
    asm("rcp.approx.f32 %0, %1;" : "=f"(r) : "f"(d));
    return fmaf(-2.0f, r, 1.0f);
}

__global__ __launch_bounds__(THREADS, 3)
void fans_kernel(const float* __restrict__ x_f,
                 const float* __restrict__ x_b,
                 const float* __restrict__ u,
                 const float* __restrict__ W0,
                 const float* __restrict__ W1,
                 const float* __restrict__ W2,
                 float* __restrict__ out)
{
    const int o   = blockIdx.y;
    const int tid = threadIdx.x;
    const int b0  = blockIdx.x * (THREADS * ROWS) + tid;
    const int b1  = b0 + THREADS;

    __shared__ float sW0[NF * ZIN];   // 3 KB (rows of 48B, 16B aligned)
    __shared__ float sW1[NF * NF];    // 16 KB
    __shared__ float sW2[NF];         // 256 B

    // ---- cooperative weight staging (vectorized) ----
    {
        const float4* g = (const float4*)(W1 + o * (NF * NF));
        float4*       s = (float4*)sW1;
        #pragma unroll
        for (int i = 0; i < (NF * NF / 4) / THREADS; i++)   // 8 iters
            s[tid + i * THREADS] = g[tid + i * THREADS];
    }
    {
        const float4* g = (const float4*)(W0 + o * (NF * ZIN));
        float4*       s = (float4*)sW0;
        for (int i = tid; i < NF * ZIN / 4; i += THREADS)   // 192 float4
            s[i] = g[i];
    }
    if (tid < NF) sW2[tid] = W2[o * NF + tid];

    // ---- build z for both rows directly from global (closed-form sorted IDX):
    //      o<=8 : e = o+s ;  o>=9 : e = (s < o-8) ? s : s+8
    //      element e<8 -> x_f[b*8+e], else x_b[b*8+e-8]. ----
    ull zp0[ZIN / 2], zp1[ZIN / 2];
    {
        float z0[ZIN], z1[ZIN];
        #pragma unroll
        for (int s = 0; s < 8; s++) {
            int e = (o <= 8) ? (o + s) : ((s < o - 8) ? s : s + 8);
            const float* p = (e < 8) ? (x_f + e) : (x_b + (e - 8));
            z0[s] = __ldg(p + b0 * 8);
            z1[s] = __ldg(p + b1 * 8);
        }
        float4 u0 = *(const float4*)(u + b0 * 4);
        float4 u1 = *(const float4*)(u + b1 * 4);
        z0[8] = u0.x; z0[9] = u0.y; z0[10] = u0.z; z0[11] = u0.w;
        z1[8] = u1.x; z1[9] = u1.y; z1[10] = u1.z; z1[11] = u1.w;
        #pragma unroll
        for (int i = 0; i < ZIN / 2; i++) {
            zp0[i] = pack2(z0[2*i], z0[2*i+1]);
            zp1[i] = pack2(z1[2*i], z1[2*i+1]);
        }
    }

    __syncthreads();   // weights visible

    // ---- layer 1: h = tanh(W0 z) for both rows; weights loaded once per pair ----
    ull hA[NF / 2], hB[NF / 2];      // packed h pairs, row0 / row1
    #pragma unroll
    for (int f = 0; f < NF; f += 2) {
        const ulonglong2* wA = (const ulonglong2*)(&sW0[(f + 0) * ZIN]);
        const ulonglong2* wB = (const ulonglong2*)(&sW0[(f + 1) * ZIN]);
        ull aA = 0ull, aB = 0ull;    // row0: features f, f+1
        ull bA = 0ull, bB = 0ull;    // row1: features f, f+1
        #pragma unroll
        for (int i = 0; i < 3; i++) {
            ulonglong2 qA = wA[i];
            ulonglong2 qB = wB[i];
            aA = fma2(zp0[2*i+0], qA.x, aA);
            aA = fma2(zp0[2*i+1], qA.y, aA);
            aB = fma2(zp0[2*i+0], qB.x, aB);
            aB = fma2(zp0[2*i+1], qB.y, aB);
            bA = fma2(zp1[2*i+0], qA.x, bA);
            bA = fma2(zp1[2*i+1], qA.y, bA);
            bB = fma2(zp1[2*i+0], qB.x, bB);
            bB = fma2(zp1[2*i+1], qB.y, bB);
        }
        float2 sA = unpack2(aA), sB = unpack2(aB);
        float2 tA = unpack2(bA), tB = unpack2(bB);
        hA[f / 2] = pack2(fast_tanh(sA.x + sA.y), fast_tanh(sB.x + sB.y));
        hB[f / 2] = pack2(fast_tanh(tA.x + tA.y), fast_tanh(tB.x + tB.y));
    }

    // ---- layer 2 + 3 fused, both rows share each W1-row load ----
    float dx0 = 0.0f, dx1 = 0.0f;
    #pragma unroll 2
    for (int f2 = 0; f2 < NF; f2++) {
        const ulonglong2* w = (const ulonglong2*)(&sW1[f2 * NF]);
        ull a0 = 0ull, a1 = 0ull, a2 = 0ull, a3 = 0ull;   // row0
        ull c0 = 0ull, c1 = 0ull, c2 = 0ull, c3 = 0ull;   // row1
        #pragma unroll
        for (int j = 0; j < 16; j += 2) {
            ulonglong2 q0 = w[j + 0];
            ulonglong2 q1 = w[j + 1];
            a0 = fma2(hA[2*j + 0], q0.x, a0);
            a1 = fma2(hA[2*j + 1], q0.y, a1);
            a2 = fma2(hA[2*j + 2], q1.x, a2);
            a3 = fma2(hA[2*j + 3], q1.y, a3);
            c0 = fma2(hB[2*j + 0], q0.x, c0);
            c1 = fma2(hB[2*j + 1], q0.y, c1);
            c2 = fma2(hB[2*j + 2], q1.x, c2);
            c3 = fma2(hB[2*j + 3], q1.y, c3);
        }
        float w2v = sW2[f2];
        {   // packed reduction tree: 3 add2 + 1 unpack + 1 add
            ull t = add2(add2(a0, a1), add2(a2, a3));
            float2 s = unpack2(t);
            dx0 = fmaf(fast_tanh(s.x + s.y), w2v, dx0);
        }
        {
            ull t = add2(add2(c0, c1), add2(c2, c3));
            float2 s = unpack2(t);
            dx1 = fmaf(fast_tanh(s.x + s.y), w2v, dx1);
        }
    }

    out[b0 * NOUT + o] = dx0;
    out[b1 * NOUT + o] = dx1;
}

extern "C" void kernel_launch(void* const* d_in, const int* in_sizes, int n_in,
                              void* d_out, int out_size) {
    const float* x_f = (const float*)d_in[0];
    const float* x_b = (const float*)d_in[1];
    const float* u   = (const float*)d_in[2];
    const float* W0  = (const float*)d_in[3];
    const float* W1  = (const float*)d_in[4];
    const float* W2  = (const float*)d_in[5];
    float* out = (float*)d_out;

    int B = in_sizes[0] / 8;                      // x_f is (B, 8)
    dim3 grid(B / (THREADS * ROWS), NOUT);
    fans_kernel<<<grid, THREADS>>>(x_f, x_b, u, W0, W1, W2, out);
}

// round 9
// speedup vs baseline: 1.8669x; 1.4980x over previous
#include <cuda_runtime.h>
#include <cuda_fp16.h>
#include <cstdint>

#define THREADS 128
#define NF 64
#define NOUT 16
// smem row strides in halves, chosen so ldmatrix 8-row phases hit distinct 16B banks
#define W1_STR 72   // 144B: 144*i mod 128 = 16i -> conflict-free
#define W0_STR 24   // 48B:  48*i  mod 128 distinct
#define Z_STR  24

__device__ __forceinline__ uint32_t smem_u32(const void* p) {
    uint32_t a;
    asm("{ .reg .u64 t; cvta.to.shared.u64 t, %1; cvt.u32.u64 %0, t; }" : "=r"(a) : "l"(p));
    return a;
}
__device__ __forceinline__ void ldm_x4(uint32_t& r0, uint32_t& r1, uint32_t& r2, uint32_t& r3,
                                       uint32_t a) {
    asm volatile("ldmatrix.sync.aligned.m8n8.x4.shared.b16 {%0,%1,%2,%3}, [%4];"
                 : "=r"(r0), "=r"(r1), "=r"(r2), "=r"(r3) : "r"(a));
}
__device__ __forceinline__ void mma16816(float* c, const uint32_t* a, uint32_t b0, uint32_t b1) {
    asm volatile("mma.sync.aligned.m16n8k16.row.col.f32.f16.f16.f32 "
                 "{%0,%1,%2,%3}, {%4,%5,%6,%7}, {%8,%9}, {%0,%1,%2,%3};"
                 : "+f"(c[0]), "+f"(c[1]), "+f"(c[2]), "+f"(c[3])
                 : "r"(a[0]), "r"(a[1]), "r"(a[2]), "r"(a[3]), "r"(b0), "r"(b1));
}

// tanh(x) = 1 - 2*rcp(2^(2x*log2e) + 1): 3 fma-pipe ops + 2 MUFU, ~1e-6 err
__device__ __forceinline__ float fast_tanh(float x) {
    float t = x * 2.8853900817779268f;
    float e;
    asm("ex2.approx.f32 %0, %1;" : "=f"(e) : "f"(t));
    float d = e + 1.0f;
    float r;
    asm("rcp.approx.f32 %0, %1;" : "=f"(r) : "f"(d));
    return fmaf(-2.0f, r, 1.0f);
}

// 2-term fp16 split of a pair of floats -> packed f16x2 hi and lo
__device__ __forceinline__ void split_pair(float a, float b, uint32_t& hi, uint32_t& lo) {
    __half ha = __float2half_rn(a), hb = __float2half_rn(b);
    __half2 H = __halves2half2(ha, hb);
    hi = *reinterpret_cast<uint32_t*>(&H);
    __half2 L = __floats2half2_rn(a - __half2float(ha), b - __half2float(hb));
    lo = *reinterpret_cast<uint32_t*>(&L);
}

__global__ __launch_bounds__(THREADS)
void fans_mma_kernel(const float* __restrict__ x_f,
                     const float* __restrict__ x_b,
                     const float* __restrict__ u,
                     const float* __restrict__ W0,
                     const float* __restrict__ W1,
                     const float* __restrict__ W2,
                     float* __restrict__ out)
{
    const int o    = blockIdx.y;
    const int tid  = threadIdx.x;
    const int w    = tid >> 5;
    const int lane = tid & 31;
    const int bbase = blockIdx.x * 128;

    __shared__ __half W1h[NF * W1_STR], W1l[NF * W1_STR];   // 9216 B each
    __shared__ __half W0h[NF * W0_STR], W0l[NF * W0_STR];   // 3072 B each
    __shared__ __half Zh[4][32 * Z_STR], Zl[4][32 * Z_STR]; // 6144 B each
    __shared__ float sW2[NF];

    // ---- stage W1 (hi/lo f16), [n=f2][k=f1], stride 72 ----
    for (int idx = tid; idx < NF * NF; idx += THREADS) {
        int n = idx >> 6, k = idx & 63;
        float wv = W1[o * (NF * NF) + idx];
        __half hi = __float2half_rn(wv);
        W1h[n * W1_STR + k] = hi;
        W1l[n * W1_STR + k] = __float2half_rn(wv - __half2float(hi));
    }
    // ---- stage W0 (hi/lo f16), [n=f][k=i], K padded 12->16, stride 24 ----
    for (int idx = tid; idx < NF * 16; idx += THREADS) {
        int n = idx >> 4, k = idx & 15;
        float wv = (k < 12) ? W0[o * (NF * 12) + n * 12 + k] : 0.0f;
        __half hi = __float2half_rn(wv);
        W0h[n * W0_STR + k] = hi;
        W0l[n * W0_STR + k] = __float2half_rn(wv - __half2float(hi));
    }
    if (tid < NF) sW2[tid] = W2[o * NF + tid];

    // ---- build z (closed-form sorted IDX) and stage Z tile (hi/lo) ----
    {
        const int b = bbase + tid;     // w*32 + lane == tid
        float z[12];
        #pragma unroll
        for (int s = 0; s < 8; s++) {
            int e = (o <= 8) ? (o + s) : ((s < o - 8) ? s : s + 8);
            const float* p = (e < 8) ? (x_f + e) : (x_b + (e - 8));
            z[s] = __ldg(p + b * 8);
        }
        float4 uu = *(const float4*)(u + b * 4);
        z[8] = uu.x; z[9] = uu.y; z[10] = uu.z; z[11] = uu.w;

        uint32_t* zh = (uint32_t*)&Zh[w][lane * Z_STR];
        uint32_t* zl = (uint32_t*)&Zl[w][lane * Z_STR];
        #pragma unroll
        for (int j = 0; j < 6; j++) {
            uint32_t hi, lo;
            split_pair(z[2 * j], z[2 * j + 1], hi, lo);
            zh[j] = hi; zl[j] = lo;
        }
        zh[6] = 0u; zh[7] = 0u; zl[6] = 0u; zl[7] = 0u;   // K pad
    }
    __syncthreads();

    // ---- A1 fragments from Z tiles (2 m-tiles of 16 rows) ----
    uint32_t aZh[2][4], aZl[2][4];
    #pragma unroll
    for (int m = 0; m < 2; m++) {
        int row = m * 16 + (lane & 15);
        int col = (lane >> 4) * 8;
        ldm_x4(aZh[m][0], aZh[m][1], aZh[m][2], aZh[m][3],
               smem_u32(&Zh[w][row * Z_STR + col]));
        ldm_x4(aZl[m][0], aZl[m][1], aZl[m][2], aZl[m][3],
               smem_u32(&Zl[w][row * Z_STR + col]));
    }

    float c[8][2][4];
    #pragma unroll
    for (int n = 0; n < 8; n++)
        #pragma unroll
        for (int m = 0; m < 2; m++)
            c[n][m][0] = c[n][m][1] = c[n][m][2] = c[n][m][3] = 0.0f;

    // ---- layer 1: C1 = Z * W0^T  (3-term fp16 split), K=16 ----
    #pragma unroll
    for (int nj = 0; nj < 4; nj++) {                 // covers n-tiles 2nj, 2nj+1
        int rown = nj * 16 + (lane & 7) + ((lane >> 4) << 3);
        int col  = ((lane >> 3) & 1) * 8;
        uint32_t bh0, bh1, bh2, bh3, bl0, bl1, bl2, bl3;
        ldm_x4(bh0, bh1, bh2, bh3, smem_u32(&W0h[rown * W0_STR + col]));
        ldm_x4(bl0, bl1, bl2, bl3, smem_u32(&W0l[rown * W0_STR + col]));
        #pragma unroll
        for (int m = 0; m < 2; m++) {
            mma16816(c[2 * nj][m],     aZh[m], bh0, bh1);
            mma16816(c[2 * nj][m],     aZl[m], bh0, bh1);
            mma16816(c[2 * nj][m],     aZh[m], bl0, bl1);
            mma16816(c[2 * nj + 1][m], aZh[m], bh2, bh3);
            mma16816(c[2 * nj + 1][m], aZl[m], bh2, bh3);
            mma16816(c[2 * nj + 1][m], aZh[m], bl2, bl3);
        }
    }

    // ---- tanh + split: C1 fragments -> A2 fragments (register chaining) ----
    uint32_t aH[4][2][4], aL[4][2][4];
    #pragma unroll
    for (int kk = 0; kk < 4; kk++)
        #pragma unroll
        for (int m = 0; m < 2; m++) {
            float t0 = fast_tanh(c[2 * kk][m][0]);
            float t1 = fast_tanh(c[2 * kk][m][1]);
            float t2 = fast_tanh(c[2 * kk][m][2]);
            float t3 = fast_tanh(c[2 * kk][m][3]);
            float t4 = fast_tanh(c[2 * kk + 1][m][0]);
            float t5 = fast_tanh(c[2 * kk + 1][m][1]);
            float t6 = fast_tanh(c[2 * kk + 1][m][2]);
            float t7 = fast_tanh(c[2 * kk + 1][m][3]);
            split_pair(t0, t1, aH[kk][m][0], aL[kk][m][0]);
            split_pair(t2, t3, aH[kk][m][1], aL[kk][m][1]);
            split_pair(t4, t5, aH[kk][m][2], aL[kk][m][2]);
            split_pair(t6, t7, aH[kk][m][3], aL[kk][m][3]);
        }

    #pragma unroll
    for (int n = 0; n < 8; n++)
        #pragma unroll
        for (int m = 0; m < 2; m++)
            c[n][m][0] = c[n][m][1] = c[n][m][2] = c[n][m][3] = 0.0f;

    // ---- layer 2: C2 = H * W1^T (3-term fp16 split), K=64 ----
    #pragma unroll
    for (int n = 0; n < 8; n++) {
        #pragma unroll
        for (int kk2 = 0; kk2 < 2; kk2++) {           // pairs of k-tiles
            int rown = n * 8 + (lane & 7);
            int col  = kk2 * 32 + (lane >> 3) * 8;
            uint32_t bh0, bh1, bh2, bh3, bl0, bl1, bl2, bl3;
            ldm_x4(bh0, bh1, bh2, bh3, smem_u32(&W1h[rown * W1_STR + col]));
            ldm_x4(bl0, bl1, bl2, bl3, smem_u32(&W1l[rown * W1_STR + col]));
            int k0 = 2 * kk2, k1 = 2 * kk2 + 1;
            #pragma unroll
            for (int m = 0; m < 2; m++) {
                mma16816(c[n][m], aH[k0][m], bh0, bh1);
                mma16816(c[n][m], aL[k0][m], bh0, bh1);
                mma16816(c[n][m], aH[k0][m], bl0, bl1);
                mma16816(c[n][m], aH[k1][m], bh2, bh3);
                mma16816(c[n][m], aL[k1][m], bh2, bh3);
                mma16816(c[n][m], aH[k1][m], bl2, bl3);
            }
        }
    }

    // ---- epilogue: dx = sum_f2 tanh(C2)*w2, quad reduce, store ----
    {
        int q = lane & 3;
        float dx[2][2] = {{0.f, 0.f}, {0.f, 0.f}};    // [m][r]
        #pragma unroll
        for (int n = 0; n < 8; n++) {
            float w2a = sW2[8 * n + 2 * q];
            float w2b = sW2[8 * n + 2 * q + 1];
            #pragma unroll
            for (int m = 0; m < 2; m++) {
                dx[m][0] = fmaf(fast_tanh(c[n][m][0]), w2a, dx[m][0]);
                dx[m][0] = fmaf(fast_tanh(c[n][m][1]), w2b, dx[m][0]);
                dx[m][1] = fmaf(fast_tanh(c[n][m][2]), w2a, dx[m][1]);
                dx[m][1] = fmaf(fast_tanh(c[n][m][3]), w2b, dx[m][1]);
            }
        }
        #pragma unroll
        for (int m = 0; m < 2; m++)
            #pragma unroll
            for (int r = 0; r < 2; r++) {
                dx[m][r] += __shfl_xor_sync(0xFFFFFFFF, dx[m][r], 1);
                dx[m][r] += __shfl_xor_sync(0xFFFFFFFF, dx[m][r], 2);
            }
        if (q == 0) {
            int rbase = bbase + w * 32 + (lane >> 2);
            #pragma unroll
            for (int m = 0; m < 2; m++) {
                out[(rbase + m * 16 + 0) * NOUT + o] = dx[m][0];
                out[(rbase + m * 16 + 8) * NOUT + o] = dx[m][1];
            }
        }
    }
}

extern "C" void kernel_launch(void* const* d_in, const int* in_sizes, int n_in,
                              void* d_out, int out_size) {
    const float* x_f = (const float*)d_in[0];
    const float* x_b = (const float*)d_in[1];
    const float* u   = (const float*)d_in[2];
    const float* W0  = (const float*)d_in[3];
    const float* W1  = (const float*)d_in[4];
    const float* W2  = (const float*)d_in[5];
    float* out = (float*)d_out;

    int B = in_sizes[0] / 8;                 // x_f is (B, 8)
    dim3 grid(B / 128, NOUT);
    fans_mma_kernel<<<grid, THREADS>>>(x_f, x_b, u, W0, W1, W2, out);
}

// round 10
// speedup vs baseline: 2.3854x; 1.2778x over previous
#include <cuda_runtime.h>
#include <cuda_fp16.h>
#include <cstdint>

#define THREADS 128
#define TILES 8      // batch tiles per CTA: weight staging amortization
#define NF 64
#define NOUT 16
// smem row strides in halves, chosen so ldmatrix 8-row phases hit distinct 16B banks
#define W1_STR 72   // 144B: 144*i mod 128 = 16i -> conflict-free
#define W0_STR 24   // 48B
#define Z_STR  24

__device__ __forceinline__ uint32_t smem_u32(const void* p) {
    uint32_t a;
    asm("{ .reg .u64 t; cvta.to.shared.u64 t, %1; cvt.u32.u64 %0, t; }" : "=r"(a) : "l"(p));
    return a;
}
__device__ __forceinline__ void ldm_x4(uint32_t& r0, uint32_t& r1, uint32_t& r2, uint32_t& r3,
                                       uint32_t a) {
    asm volatile("ldmatrix.sync.aligned.m8n8.x4.shared.b16 {%0,%1,%2,%3}, [%4];"
                 : "=r"(r0), "=r"(r1), "=r"(r2), "=r"(r3) : "r"(a));
}
__device__ __forceinline__ void mma16816(float* c, const uint32_t* a, uint32_t b0, uint32_t b1) {
    asm volatile("mma.sync.aligned.m16n8k16.row.col.f32.f16.f16.f32 "
                 "{%0,%1,%2,%3}, {%4,%5,%6,%7}, {%8,%9}, {%0,%1,%2,%3};"
                 : "+f"(c[0]), "+f"(c[1]), "+f"(c[2]), "+f"(c[3])
                 : "r"(a[0]), "r"(a[1]), "r"(a[2]), "r"(a[3]), "r"(b0), "r"(b1));
}

// tanh(x) = 1 - 2*rcp(2^(2x*log2e) + 1): 3 fma-pipe ops + 2 MUFU, ~1e-6 err
__device__ __forceinline__ float fast_tanh(float x) {
    float t = x * 2.8853900817779268f;
    float e;
    asm("ex2.approx.f32 %0, %1;" : "=f"(e) : "f"(t));
    float d = e + 1.0f;
    float r;
    asm("rcp.approx.f32 %0, %1;" : "=f"(r) : "f"(d));
    return fmaf(-2.0f, r, 1.0f);
}

// 2-term fp16 split of a pair of floats -> packed f16x2 hi and lo
__device__ __forceinline__ void split_pair(float a, float b, uint32_t& hi, uint32_t& lo) {
    __half ha = __float2half_rn(a), hb = __float2half_rn(b);
    __half2 H = __halves2half2(ha, hb);
    hi = *reinterpret_cast<uint32_t*>(&H);
    __half2 L = __floats2half2_rn(a - __half2float(ha), b - __half2float(hb));
    lo = *reinterpret_cast<uint32_t*>(&L);
}

__global__ __launch_bounds__(THREADS, 2)
void fans_mma_kernel(const float* __restrict__ x_f,
                     const float* __restrict__ x_b,
                     const float* __restrict__ u,
                     const float* __restrict__ W0,
                     const float* __restrict__ W1,
                     const float* __restrict__ W2,
                     float* __restrict__ out)
{
    const int o    = blockIdx.y;
    const int tid  = threadIdx.x;
    const int w    = tid >> 5;
    const int lane = tid & 31;

    __shared__ __half W1h[NF * W1_STR], W1l[NF * W1_STR];   // 9216 B each
    __shared__ __half W0h[NF * W0_STR], W0l[NF * W0_STR];   // 3072 B each
    __shared__ __half Zh[4][32 * Z_STR], Zl[4][32 * Z_STR]; // 6144 B each
    __shared__ float sW2[NF];

    // ---- stage W1 (hi/lo f16), [n=f2][k=f1], ONCE per CTA ----
    for (int idx = tid; idx < NF * NF; idx += THREADS) {
        int n = idx >> 6, k = idx & 63;
        float wv = W1[o * (NF * NF) + idx];
        __half hi = __float2half_rn(wv);
        W1h[n * W1_STR + k] = hi;
        W1l[n * W1_STR + k] = __float2half_rn(wv - __half2float(hi));
    }
    // ---- stage W0 (hi/lo f16), [n=f][k=i], K padded 12->16 ----
    for (int idx = tid; idx < NF * 16; idx += THREADS) {
        int n = idx >> 4, k = idx & 15;
        float wv = (k < 12) ? W0[o * (NF * 12) + n * 12 + k] : 0.0f;
        __half hi = __float2half_rn(wv);
        W0h[n * W0_STR + k] = hi;
        W0l[n * W0_STR + k] = __float2half_rn(wv - __half2float(hi));
    }
    if (tid < NF) sW2[tid] = W2[o * NF + tid];
    __syncthreads();

    // ================= persistent loop over batch tiles =================
    for (int t = 0; t < TILES; t++) {
        const int bbase = (blockIdx.x * TILES + t) * 128;

        // ---- build z (closed-form sorted IDX) and stage Z tile (hi/lo) ----
        {
            const int b = bbase + tid;
            float z[12];
            #pragma unroll
            for (int s = 0; s < 8; s++) {
                int e = (o <= 8) ? (o + s) : ((s < o - 8) ? s : s + 8);
                const float* p = (e < 8) ? (x_f + e) : (x_b + (e - 8));
                z[s] = __ldg(p + b * 8);
            }
            float4 uu = *(const float4*)(u + b * 4);
            z[8] = uu.x; z[9] = uu.y; z[10] = uu.z; z[11] = uu.w;

            uint32_t* zh = (uint32_t*)&Zh[w][lane * Z_STR];
            uint32_t* zl = (uint32_t*)&Zl[w][lane * Z_STR];
            #pragma unroll
            for (int j = 0; j < 6; j++) {
                uint32_t hi, lo;
                split_pair(z[2 * j], z[2 * j + 1], hi, lo);
                zh[j] = hi; zl[j] = lo;
            }
            zh[6] = 0u; zh[7] = 0u; zl[6] = 0u; zl[7] = 0u;   // K pad
        }
        __syncwarp();   // Z slab is warp-local

        // ---- A1 fragments from Z tiles (2 m-tiles of 16 rows) ----
        uint32_t aZh[2][4], aZl[2][4];
        #pragma unroll
        for (int m = 0; m < 2; m++) {
            int row = m * 16 + (lane & 15);
            int col = (lane >> 4) * 8;
            ldm_x4(aZh[m][0], aZh[m][1], aZh[m][2], aZh[m][3],
                   smem_u32(&Zh[w][row * Z_STR + col]));
            ldm_x4(aZl[m][0], aZl[m][1], aZl[m][2], aZl[m][3],
                   smem_u32(&Zl[w][row * Z_STR + col]));
        }
        __syncwarp();   // all lanes done reading Z before next tile overwrites

        float c[8][2][4];
        #pragma unroll
        for (int n = 0; n < 8; n++)
            #pragma unroll
            for (int m = 0; m < 2; m++)
                c[n][m][0] = c[n][m][1] = c[n][m][2] = c[n][m][3] = 0.0f;

        // ---- layer 1: C1 = Z * W0^T  (3-term fp16 split), K=16 ----
        #pragma unroll
        for (int nj = 0; nj < 4; nj++) {
            int rown = nj * 16 + (lane & 7) + ((lane >> 4) << 3);
            int col  = ((lane >> 3) & 1) * 8;
            uint32_t bh0, bh1, bh2, bh3, bl0, bl1, bl2, bl3;
            ldm_x4(bh0, bh1, bh2, bh3, smem_u32(&W0h[rown * W0_STR + col]));
            ldm_x4(bl0, bl1, bl2, bl3, smem_u32(&W0l[rown * W0_STR + col]));
            #pragma unroll
            for (int m = 0; m < 2; m++) {
                mma16816(c[2 * nj][m],     aZh[m], bh0, bh1);
                mma16816(c[2 * nj][m],     aZl[m], bh0, bh1);
                mma16816(c[2 * nj][m],     aZh[m], bl0, bl1);
                mma16816(c[2 * nj + 1][m], aZh[m], bh2, bh3);
                mma16816(c[2 * nj + 1][m], aZl[m], bh2, bh3);
                mma16816(c[2 * nj + 1][m], aZh[m], bl2, bl3);
            }
        }

        // ---- tanh + split: C1 fragments -> A2 fragments (register chaining) ----
        uint32_t aH[4][2][4], aL[4][2][4];
        #pragma unroll
        for (int kk = 0; kk < 4; kk++)
            #pragma unroll
            for (int m = 0; m < 2; m++) {
                float t0 = fast_tanh(c[2 * kk][m][0]);
                float t1 = fast_tanh(c[2 * kk][m][1]);
                float t2 = fast_tanh(c[2 * kk][m][2]);
                float t3 = fast_tanh(c[2 * kk][m][3]);
                float t4 = fast_tanh(c[2 * kk + 1][m][0]);
                float t5 = fast_tanh(c[2 * kk + 1][m][1]);
                float t6 = fast_tanh(c[2 * kk + 1][m][2]);
                float t7 = fast_tanh(c[2 * kk + 1][m][3]);
                split_pair(t0, t1, aH[kk][m][0], aL[kk][m][0]);
                split_pair(t2, t3, aH[kk][m][1], aL[kk][m][1]);
                split_pair(t4, t5, aH[kk][m][2], aL[kk][m][2]);
                split_pair(t6, t7, aH[kk][m][3], aL[kk][m][3]);
            }

        #pragma unroll
        for (int n = 0; n < 8; n++)
            #pragma unroll
            for (int m = 0; m < 2; m++)
                c[n][m][0] = c[n][m][1] = c[n][m][2] = c[n][m][3] = 0.0f;

        // ---- layer 2: C2 = H * W1^T (3-term fp16 split), K=64 ----
        #pragma unroll
        for (int n = 0; n < 8; n++) {
            #pragma unroll
            for (int kk2 = 0; kk2 < 2; kk2++) {
                int rown = n * 8 + (lane & 7);
                int col  = kk2 * 32 + (lane >> 3) * 8;
                uint32_t bh0, bh1, bh2, bh3, bl0, bl1, bl2, bl3;
                ldm_x4(bh0, bh1, bh2, bh3, smem_u32(&W1h[rown * W1_STR + col]));
                ldm_x4(bl0, bl1, bl2, bl3, smem_u32(&W1l[rown * W1_STR + col]));
                int k0 = 2 * kk2, k1 = 2 * kk2 + 1;
                #pragma unroll
                for (int m = 0; m < 2; m++) {
                    mma16816(c[n][m], aH[k0][m], bh0, bh1);
                    mma16816(c[n][m], aL[k0][m], bh0, bh1);
                    mma16816(c[n][m], aH[k0][m], bl0, bl1);
                    mma16816(c[n][m], aH[k1][m], bh2, bh3);
                    mma16816(c[n][m], aL[k1][m], bh2, bh3);
                    mma16816(c[n][m], aH[k1][m], bl2, bl3);
                }
            }
        }

        // ---- epilogue: dx = sum_f2 tanh(C2)*w2, quad reduce, store ----
        {
            int q = lane & 3;
            float dx[2][2] = {{0.f, 0.f}, {0.f, 0.f}};    // [m][r]
            #pragma unroll
            for (int n = 0; n < 8; n++) {
                float w2a = sW2[8 * n + 2 * q];
                float w2b = sW2[8 * n + 2 * q + 1];
                #pragma unroll
                for (int m = 0; m < 2; m++) {
                    dx[m][0] = fmaf(fast_tanh(c[n][m][0]), w2a, dx[m][0]);
                    dx[m][0] = fmaf(fast_tanh(c[n][m][1]), w2b, dx[m][0]);
                    dx[m][1] = fmaf(fast_tanh(c[n][m][2]), w2a, dx[m][1]);
                    dx[m][1] = fmaf(fast_tanh(c[n][m][3]), w2b, dx[m][1]);
                }
            }
            #pragma unroll
            for (int m = 0; m < 2; m++)
                #pragma unroll
                for (int r = 0; r < 2; r++) {
                    dx[m][r] += __shfl_xor_sync(0xFFFFFFFF, dx[m][r], 1);
                    dx[m][r] += __shfl_xor_sync(0xFFFFFFFF, dx[m][r], 2);
                }
            if (q == 0) {
                int rbase = bbase + w * 32 + (lane >> 2);
                #pragma unroll
                for (int m = 0; m < 2; m++) {
                    out[(rbase + m * 16 + 0) * NOUT + o] = dx[m][0];
                    out[(rbase + m * 16 + 8) * NOUT + o] = dx[m][1];
                }
            }
        }
    }
}

extern "C" void kernel_launch(void* const* d_in, const int* in_sizes, int n_in,
                              void* d_out, int out_size) {
    const float* x_f = (const float*)d_in[0];
    const float* x_b = (const float*)d_in[1];
    const float* u   = (const float*)d_in[2];
    const float* W0  = (const float*)d_in[3];
    const float* W1  = (const float*)d_in[4];
    const float* W2  = (const float*)d_in[5];
    float* out = (float*)d_out;

    int B = in_sizes[0] / 8;                 // x_f is (B, 8)
    dim3 grid(B / (128 * TILES), NOUT);
    fans_mma_kernel<<<grid, THREADS>>>(x_f, x_b, u, W0, W1, W2, out);
}

// round 11
// speedup vs baseline: 2.7148x; 1.1381x over previous
#include <cuda_runtime.h>
#include <cuda_fp16.h>
#include <cstdint>

#define THREADS 128
#define TILES 8      // batch tiles per CTA: weight staging amortization
#define NF 64
#define NOUT 16
// smem row strides in halves, chosen so ldmatrix 8-row phases hit distinct 16B banks
#define W1_STR 72   // 144B: 144*i mod 128 = 16i -> conflict-free
#define W0_STR 24   // 48B
#define Z_STR  24

__device__ __forceinline__ uint32_t smem_u32(const void* p) {
    uint32_t a;
    asm("{ .reg .u64 t; cvta.to.shared.u64 t, %1; cvt.u32.u64 %0, t; }" : "=r"(a) : "l"(p));
    return a;
}
__device__ __forceinline__ void ldm_x4(uint32_t& r0, uint32_t& r1, uint32_t& r2, uint32_t& r3,
                                       uint32_t a) {
    asm volatile("ldmatrix.sync.aligned.m8n8.x4.shared.b16 {%0,%1,%2,%3}, [%4];"
                 : "=r"(r0), "=r"(r1), "=r"(r2), "=r"(r3) : "r"(a));
}
__device__ __forceinline__ void mma16816(float* c, const uint32_t* a, uint32_t b0, uint32_t b1) {
    asm volatile("mma.sync.aligned.m16n8k16.row.col.f32.f16.f16.f32 "
                 "{%0,%1,%2,%3}, {%4,%5,%6,%7}, {%8,%9}, {%0,%1,%2,%3};"
                 : "+f"(c[0]), "+f"(c[1]), "+f"(c[2]), "+f"(c[3])
                 : "r"(a[0]), "r"(a[1]), "r"(a[2]), "r"(a[3]), "r"(b0), "r"(b1));
}

// tanh(x) = 1 - 2*rcp(2^(2x*log2e) + 1): 3 fma-pipe ops + 2 MUFU, ~1e-6 err
__device__ __forceinline__ float fast_tanh(float x) {
    float t = x * 2.8853900817779268f;
    float e;
    asm("ex2.approx.f32 %0, %1;" : "=f"(e) : "f"(t));
    float d = e + 1.0f;
    float r;
    asm("rcp.approx.f32 %0, %1;" : "=f"(r) : "f"(d));
    return fmaf(-2.0f, r, 1.0f);
}

__device__ __forceinline__ uint32_t pack_h2(float a, float b) {
    __half2 H = __floats2half2_rn(a, b);   // low = a
    return *reinterpret_cast<uint32_t*>(&H);
}

__global__ __launch_bounds__(THREADS, 2)
void fans_mma_kernel(const float* __restrict__ x_f,
                     const float* __restrict__ x_b,
                     const float* __restrict__ u,
                     const float* __restrict__ W0,
                     const float* __restrict__ W1,
                     const float* __restrict__ W2,
                     float* __restrict__ out)
{
    const int o    = blockIdx.y;
    const int tid  = threadIdx.x;
    const int w    = tid >> 5;
    const int lane = tid & 31;

    __shared__ __half W1h[NF * W1_STR], W1l[NF * W1_STR];   // 9216 B each
    __shared__ __half W0h[NF * W0_STR], W0l[NF * W0_STR];   // 3072 B each
    __shared__ __half Zh[4][32 * Z_STR];                    // 6144 B (A hi only)
    __shared__ float sW2[NF];

    // ---- stage W1 (hi/lo f16 -> weights effectively fp32), ONCE per CTA ----
    for (int idx = tid; idx < NF * NF; idx += THREADS) {
        int n = idx >> 6, k = idx & 63;
        float wv = W1[o * (NF * NF) + idx];
        __half hi = __float2half_rn(wv);
        W1h[n * W1_STR + k] = hi;
        W1l[n * W1_STR + k] = __float2half_rn(wv - __half2float(hi));
    }
    // ---- stage W0 (hi/lo f16), [n=f][k=i], K padded 12->16 ----
    for (int idx = tid; idx < NF * 16; idx += THREADS) {
        int n = idx >> 4, k = idx & 15;
        float wv = (k < 12) ? W0[o * (NF * 12) + n * 12 + k] : 0.0f;
        __half hi = __float2half_rn(wv);
        W0h[n * W0_STR + k] = hi;
        W0l[n * W0_STR + k] = __float2half_rn(wv - __half2float(hi));
    }
    if (tid < NF) sW2[tid] = W2[o * NF + tid];
    __syncthreads();

    // ================= persistent loop over batch tiles =================
    for (int t = 0; t < TILES; t++) {
        const int bbase = (blockIdx.x * TILES + t) * 128;

        // ---- build z (closed-form sorted IDX) and stage Z tile (fp16 hi only) ----
        {
            const int b = bbase + tid;
            float z[12];
            #pragma unroll
            for (int s = 0; s < 8; s++) {
                int e = (o <= 8) ? (o + s) : ((s < o - 8) ? s : s + 8);
                const float* p = (e < 8) ? (x_f + e) : (x_b + (e - 8));
                z[s] = __ldg(p + b * 8);
            }
            float4 uu = *(const float4*)(u + b * 4);
            z[8] = uu.x; z[9] = uu.y; z[10] = uu.z; z[11] = uu.w;

            uint32_t* zh = (uint32_t*)&Zh[w][lane * Z_STR];
            #pragma unroll
            for (int j = 0; j < 6; j++)
                zh[j] = pack_h2(z[2 * j], z[2 * j + 1]);
            zh[6] = 0u; zh[7] = 0u;   // K pad
        }
        __syncwarp();   // Z slab is warp-local

        // ---- A1 fragments from Z tile (2 m-tiles of 16 rows) ----
        uint32_t aZh[2][4];
        #pragma unroll
        for (int m = 0; m < 2; m++) {
            int row = m * 16 + (lane & 15);
            int col = (lane >> 4) * 8;
            ldm_x4(aZh[m][0], aZh[m][1], aZh[m][2], aZh[m][3],
                   smem_u32(&Zh[w][row * Z_STR + col]));
        }
        __syncwarp();   // all lanes done reading Z before next tile overwrites

        float c[8][2][4];
        #pragma unroll
        for (int n = 0; n < 8; n++)
            #pragma unroll
            for (int m = 0; m < 2; m++)
                c[n][m][0] = c[n][m][1] = c[n][m][2] = c[n][m][3] = 0.0f;

        // ---- layer 1: C1 = Zh * (W0h + W0l)^T, K=16 ----
        #pragma unroll
        for (int nj = 0; nj < 4; nj++) {
            int rown = nj * 16 + (lane & 7) + ((lane >> 4) << 3);
            int col  = ((lane >> 3) & 1) * 8;
            uint32_t bh0, bh1, bh2, bh3, bl0, bl1, bl2, bl3;
            ldm_x4(bh0, bh1, bh2, bh3, smem_u32(&W0h[rown * W0_STR + col]));
            ldm_x4(bl0, bl1, bl2, bl3, smem_u32(&W0l[rown * W0_STR + col]));
            #pragma unroll
            for (int m = 0; m < 2; m++) {
                mma16816(c[2 * nj][m],     aZh[m], bh0, bh1);
                mma16816(c[2 * nj][m],     aZh[m], bl0, bl1);
                mma16816(c[2 * nj + 1][m], aZh[m], bh2, bh3);
                mma16816(c[2 * nj + 1][m], aZh[m], bl2, bl3);
            }
        }

        // ---- tanh: C1 fragments -> A2 fragments (hi only, register chaining) ----
        uint32_t aH[4][2][4];
        #pragma unroll
        for (int kk = 0; kk < 4; kk++)
            #pragma unroll
            for (int m = 0; m < 2; m++) {
                aH[kk][m][0] = pack_h2(fast_tanh(c[2 * kk][m][0]),
                                       fast_tanh(c[2 * kk][m][1]));
                aH[kk][m][1] = pack_h2(fast_tanh(c[2 * kk][m][2]),
                                       fast_tanh(c[2 * kk][m][3]));
                aH[kk][m][2] = pack_h2(fast_tanh(c[2 * kk + 1][m][0]),
                                       fast_tanh(c[2 * kk + 1][m][1]));
                aH[kk][m][3] = pack_h2(fast_tanh(c[2 * kk + 1][m][2]),
                                       fast_tanh(c[2 * kk + 1][m][3]));
            }

        #pragma unroll
        for (int n = 0; n < 8; n++)
            #pragma unroll
            for (int m = 0; m < 2; m++)
                c[n][m][0] = c[n][m][1] = c[n][m][2] = c[n][m][3] = 0.0f;

        // ---- layer 2: C2 = Hh * (W1h + W1l)^T, K=64 ----
        #pragma unroll
        for (int n = 0; n < 8; n++) {
            #pragma unroll
            for (int kk2 = 0; kk2 < 2; kk2++) {
                int rown = n * 8 + (lane & 7);
                int col  = kk2 * 32 + (lane >> 3) * 8;
                uint32_t bh0, bh1, bh2, bh3, bl0, bl1, bl2, bl3;
                ldm_x4(bh0, bh1, bh2, bh3, smem_u32(&W1h[rown * W1_STR + col]));
                ldm_x4(bl0, bl1, bl2, bl3, smem_u32(&W1l[rown * W1_STR + col]));
                int k0 = 2 * kk2, k1 = 2 * kk2 + 1;
                #pragma unroll
                for (int m = 0; m < 2; m++) {
                    mma16816(c[n][m], aH[k0][m], bh0, bh1);
                    mma16816(c[n][m], aH[k0][m], bl0, bl1);
                    mma16816(c[n][m], aH[k1][m], bh2, bh3);
                    mma16816(c[n][m], aH[k1][m], bl2, bl3);
                }
            }
        }

        // ---- epilogue: dx = sum_f2 tanh(C2)*w2, quad reduce, store ----
        {
            int q = lane & 3;
            float dx[2][2] = {{0.f, 0.f}, {0.f, 0.f}};    // [m][r]
            #pragma unroll
            for (int n = 0; n < 8; n++) {
                float w2a = sW2[8 * n + 2 * q];
                float w2b = sW2[8 * n + 2 * q + 1];
                #pragma unroll
                for (int m = 0; m < 2; m++) {
                    dx[m][0] = fmaf(fast_tanh(c[n][m][0]), w2a, dx[m][0]);
                    dx[m][0] = fmaf(fast_tanh(c[n][m][1]), w2b, dx[m][0]);
                    dx[m][1] = fmaf(fast_tanh(c[n][m][2]), w2a, dx[m][1]);
                    dx[m][1] = fmaf(fast_tanh(c[n][m][3]), w2b, dx[m][1]);
                }
            }
            #pragma unroll
            for (int m = 0; m < 2; m++)
                #pragma unroll
                for (int r = 0; r < 2; r++) {
                    dx[m][r] += __shfl_xor_sync(0xFFFFFFFF, dx[m][r], 1);
                    dx[m][r] += __shfl_xor_sync(0xFFFFFFFF, dx[m][r], 2);
                }
            if (q == 0) {
                int rbase = bbase + w * 32 + (lane >> 2);
                #pragma unroll
                for (int m = 0; m < 2; m++) {
                    out[(rbase + m * 16 + 0) * NOUT + o] = dx[m][0];
                    out[(rbase + m * 16 + 8) * NOUT + o] = dx[m][1];
                }
            }
        }
    }
}

extern "C" void kernel_launch(void* const* d_in, const int* in_sizes, int n_in,
                              void* d_out, int out_size) {
    const float* x_f = (const float*)d_in[0];
    const float* x_b = (const float*)d_in[1];
    const float* u   = (const float*)d_in[2];
    const float* W0  = (const float*)d_in[3];
    const float* W1  = (const float*)d_in[4];
    const float* W2  = (const float*)d_in[5];
    float* out = (float*)d_out;

    int B = in_sizes[0] / 8;                 // x_f is (B, 8)
    dim3 grid(B / (128 * TILES), NOUT);
    fans_mma_kernel<<<grid, THREADS>>>(x_f, x_b, u, W0, W1, W2, out);
}